// round 3
// baseline (speedup 1.0000x reference)
#include <cuda_runtime.h>
#include <math.h>

#define BATCH 16
#define NNODE 512
#define IDIM  512
#define HDIM  1024

#define RNB 148     // persistent blocks (<= GB300 152 SMs, co-resident)
#define RNT 256
#define TM  64
#define TN  64
#define KC  16

// ---------------- device scratch (no allocations allowed) ----------------
__device__ float g_Vcat[3u * HDIM * HDIM];        // [g][k][n] = V_g[k][n], 12.6 MB
__device__ float g_inp0f[BATCH * HDIM];
__device__ float g_inp0o[BATCH * HDIM];
__device__ float g_inp0z[BATCH * HDIM];
__device__ float g_tree_c[BATCH * NNODE * HDIM];  // 33.5 MB
__device__ int   g_sched[BATCH * NNODE];          // (b<<16)|i, sorted by level
__device__ int   g_level_off[NNODE + 1];
__device__ int   g_num_levels;
__device__ unsigned int g_bar;

__device__ __forceinline__ float sigmoidf_(float x) { return 1.0f / (1.0f + expf(-x)); }

// ---------------- reset (graph replays must start clean) ----------------
__global__ void reset_kernel() { g_bar = 0u; }

// ---------------- level computation + counting-sort schedule ----------------
__global__ void setup_kernel(const int* __restrict__ conn) {
    __shared__ unsigned short lvl[BATCH][NNODE];  // 16 KB
    __shared__ int counts[NNODE];
    __shared__ int offs[NNODE + 1];
    __shared__ int cur[NNODE];
    int tid = threadIdx.x;
    for (int l = tid; l < NNODE; l += blockDim.x) counts[l] = 0;
    __syncthreads();
    if (tid < BATCH) {
        int b = tid;
        lvl[b][0] = 0;
        for (int i = 1; i < NNODE; i++) {
            int p = conn[b * NNODE + i];     // guaranteed p < i
            lvl[b][i] = (unsigned short)(lvl[b][p] + 1);
        }
    }
    __syncthreads();
    for (int t = tid; t < BATCH * NNODE; t += blockDim.x) {
        int i = t & (NNODE - 1);
        if (i != 0) atomicAdd(&counts[lvl[t >> 9][i]], 1);
    }
    __syncthreads();
    if (tid == 0) {
        int acc = 0, maxl = 0;
        for (int l = 0; l < NNODE; l++) {
            offs[l] = acc;
            acc += counts[l];
            if (counts[l] > 0) maxl = l;
        }
        offs[NNODE] = acc;
        g_num_levels = maxl + 1;
    }
    __syncthreads();
    for (int l = tid; l <= NNODE; l += blockDim.x) g_level_off[l] = offs[l];
    for (int l = tid; l < NNODE; l += blockDim.x) cur[l] = offs[l];
    __syncthreads();
    for (int t = tid; t < BATCH * NNODE; t += blockDim.x) {
        int b = t >> 9, i = t & (NNODE - 1);
        if (i != 0) {
            int pos = atomicAdd(&cur[lvl[b][i]], 1);
            g_sched[pos] = (b << 16) | i;
        }
    }
}

// ---------------- f0/o0/z0 (only node 0 is ever used!) + root h/c ----------------
__global__ void inp0_kernel(const float* __restrict__ emb,
                            const float* __restrict__ Wf, const float* __restrict__ bf,
                            const float* __restrict__ Wo, const float* __restrict__ bo,
                            const float* __restrict__ Wz, const float* __restrict__ bz,
                            float* __restrict__ tree_h) {
    int t = blockIdx.x * blockDim.x + threadIdx.x;   // 16384 threads: (b, n)
    int b = t >> 10, n = t & (HDIM - 1);
    const float* x = emb + (size_t)b * NNODE * IDIM; // row (b, node 0)
    float af = bf[n], ao = bo[n], az = bz[n];
#pragma unroll 8
    for (int k = 0; k < IDIM; k++) {
        float xv = __ldg(&x[k]);
        af = fmaf(xv, Wf[k * HDIM + n], af);
        ao = fmaf(xv, Wo[k * HDIM + n], ao);
        az = fmaf(xv, Wz[k * HDIM + n], az);
    }
    g_inp0f[t] = af; g_inp0o[t] = ao; g_inp0z[t] = az;
    float f = sigmoidf_(af), o = sigmoidf_(ao), z = tanhf(az);
    float c = z * (1.0f - f);
    float h = o * tanhf(c);
    tree_h[(b * NNODE) * HDIM + n] = h;
    g_tree_c[(b * NNODE) * HDIM + n] = c;
}

// ---------------- V_g = T_g^T @ T_g, stored as g_Vcat[g][k][n] ----------------
__global__ void v_kernel(const float* __restrict__ Tf,
                         const float* __restrict__ To,
                         const float* __restrict__ Tz) {
    int g = blockIdx.x >> 8;          // 3 gates x 256 tiles
    int tile = blockIdx.x & 255;
    int r0 = (tile >> 4) << 6, c0 = (tile & 15) << 6;
    const float* T = (g == 0) ? Tf : (g == 1) ? To : Tz;
    __shared__ float Ar[KC][64];
    __shared__ float Ac[KC][64];
    float acc[4][4];
#pragma unroll
    for (int i = 0; i < 4; i++)
#pragma unroll
        for (int j = 0; j < 4; j++) acc[i][j] = 0.0f;
    int tm = threadIdx.x >> 4, tn = threadIdx.x & 15;
    for (int j0 = 0; j0 < HDIM; j0 += KC) {
        for (int idx = threadIdx.x; idx < KC * 64; idx += 256) {
            int jj = idx >> 6, col = idx & 63;
            Ar[jj][col] = T[(j0 + jj) * HDIM + r0 + col];
            Ac[jj][col] = T[(j0 + jj) * HDIM + c0 + col];
        }
        __syncthreads();
#pragma unroll
        for (int j = 0; j < KC; j++) {
            float4 a4 = *(const float4*)&Ar[j][tm << 2];
            float4 b4 = *(const float4*)&Ac[j][tn << 2];
            float av[4] = {a4.x, a4.y, a4.z, a4.w};
            float bv[4] = {b4.x, b4.y, b4.z, b4.w};
#pragma unroll
            for (int i = 0; i < 4; i++)
#pragma unroll
                for (int jj = 0; jj < 4; jj++)
                    acc[i][jj] = fmaf(av[i], bv[jj], acc[i][jj]);
        }
        __syncthreads();
    }
#pragma unroll
    for (int i = 0; i < 4; i++) {
        float4 v = make_float4(acc[i][0], acc[i][1], acc[i][2], acc[i][3]);
        *(float4*)&g_Vcat[(size_t)((g << 10) + r0 + (tm << 2) + i) * HDIM + c0 + (tn << 2)] = v;
    }
}

// ---------------- persistent level-scheduled recurrence ----------------
// Per level: batched GEMM  PH[M x 1024] @ Vcat[1024 x (3x1024)]  with gather on
// the A operand (parent rows) and a fused LSTM-cell epilogue + scatter.
__global__ void __launch_bounds__(RNT, 1)
recur_kernel(const int* __restrict__ conn, float* __restrict__ tree_h) {
    __shared__ float As[KC][TM];            // [k][m], gathered parent h
    __shared__ float Bs[3][KC][TN];         // [gate][k][n]
    __shared__ int s_prow[TM];              // parent row * HDIM
    __shared__ int s_irow[TM];              // node   row * HDIM
    __shared__ int s_bn[TM];                // b * HDIM

    int tid = threadIdx.x;
    int tm = tid >> 4, tn = tid & 15;       // 16x16 thread grid, 4x4 micro-tile
    int num_lv = g_num_levels;
    unsigned sync_no = 0;

    for (int lv = 1; lv < num_lv; lv++) {
        int off = g_level_off[lv];
        int cnt = g_level_off[lv + 1] - off;
        int mtiles = (cnt + TM - 1) / TM;
        int total = mtiles << 4;            // x 16 n-tiles

        for (int t = blockIdx.x; t < total; t += RNB) {
            int mt = t >> 4, nt = t & 15;
            int n0 = nt << 6;
            int mrel = mt * TM;

            if (tid < TM) {
                int mi = off + mrel + tid;
                int mclamp = off + cnt - 1;
                if (mi > mclamp) mi = mclamp;   // harmless duplicate for tail
                int s = g_sched[mi];
                int b = s >> 16, i = s & 0xFFFF;
                int p = conn[(b << 9) + i];
                s_prow[tid] = ((b << 9) + p) << 10;
                s_irow[tid] = ((b << 9) + i) << 10;
                s_bn[tid]   = b << 10;
            }
            __syncthreads();

            float acc[3][4][4];
#pragma unroll
            for (int g = 0; g < 3; g++)
#pragma unroll
                for (int i = 0; i < 4; i++)
#pragma unroll
                    for (int j = 0; j < 4; j++) acc[g][i][j] = 0.0f;

            int lm  = tid & 63;             // A-load: m
            int lk4 = (tid >> 6) << 2;      // A-load: k base (0,4,8,12)
            int ln4 = (tid & 15) << 2;      // B-load: n base
            int lr  = tid >> 4;             // B-load: row 0..15

            for (int k0 = 0; k0 < HDIM; k0 += KC) {
                // gather A tile (parent h rows)
                float4 av = *(const float4*)(tree_h + s_prow[lm] + k0 + lk4);
                As[lk4 + 0][lm] = av.x;
                As[lk4 + 1][lm] = av.y;
                As[lk4 + 2][lm] = av.z;
                As[lk4 + 3][lm] = av.w;
                // B tiles: 3 gates x KC x TN
#pragma unroll
                for (int p = 0; p < 3; p++) {
                    int row = (p << 4) + lr;          // 0..47
                    int gg = row >> 4, kk = row & 15;
                    float4 bv = *(const float4*)(g_Vcat +
                        (size_t)((gg << 10) + k0 + kk) * HDIM + n0 + ln4);
                    *(float4*)&Bs[gg][kk][ln4] = bv;
                }
                __syncthreads();
#pragma unroll
                for (int k = 0; k < KC; k++) {
                    float4 a4 = *(const float4*)&As[k][tm << 2];
                    float4 f4 = *(const float4*)&Bs[0][k][tn << 2];
                    float4 o4 = *(const float4*)&Bs[1][k][tn << 2];
                    float4 z4 = *(const float4*)&Bs[2][k][tn << 2];
                    float a[4]  = {a4.x, a4.y, a4.z, a4.w};
                    float bf_[4] = {f4.x, f4.y, f4.z, f4.w};
                    float bo_[4] = {o4.x, o4.y, o4.z, o4.w};
                    float bz_[4] = {z4.x, z4.y, z4.z, z4.w};
#pragma unroll
                    for (int i = 0; i < 4; i++)
#pragma unroll
                        for (int j = 0; j < 4; j++) {
                            acc[0][i][j] = fmaf(a[i], bf_[j], acc[0][i][j]);
                            acc[1][i][j] = fmaf(a[i], bo_[j], acc[1][i][j]);
                            acc[2][i][j] = fmaf(a[i], bz_[j], acc[2][i][j]);
                        }
                }
                __syncthreads();
            }

            // fused LSTM-cell epilogue + scatter
            int colbase = n0 + (tn << 2);
#pragma unroll
            for (int i = 0; i < 4; i++) {
                int m = (tm << 2) + i;
                if (mrel + m < cnt) {
                    int bn = s_bn[m] + colbase;
                    float4 F0 = *(const float4*)(g_inp0f + bn);
                    float4 O0 = *(const float4*)(g_inp0o + bn);
                    float4 Z0 = *(const float4*)(g_inp0z + bn);
                    float4 PC = *(const float4*)(g_tree_c + s_prow[m] + colbase);
                    float f0a[4] = {F0.x, F0.y, F0.z, F0.w};
                    float o0a[4] = {O0.x, O0.y, O0.z, O0.w};
                    float z0a[4] = {Z0.x, Z0.y, Z0.z, Z0.w};
                    float pca[4] = {PC.x, PC.y, PC.z, PC.w};
                    float hv[4], cv[4];
#pragma unroll
                    for (int j = 0; j < 4; j++) {
                        float f = sigmoidf_(acc[0][i][j] + f0a[j]);
                        float o = sigmoidf_(acc[1][i][j] + o0a[j]);
                        float z = tanhf(acc[2][i][j] + z0a[j]);
                        float c = pca[j] * f + z * (1.0f - f);
                        cv[j] = c;
                        hv[j] = o * tanhf(c);
                    }
                    *(float4*)(tree_h   + s_irow[m] + colbase) = make_float4(hv[0], hv[1], hv[2], hv[3]);
                    *(float4*)(g_tree_c + s_irow[m] + colbase) = make_float4(cv[0], cv[1], cv[2], cv[3]);
                }
            }
            __syncthreads();   // protect smem meta for next tile
        }

        // ---- grid barrier (cumulative counter; reset by reset_kernel) ----
        sync_no++;
        __syncthreads();
        if (tid == 0) {
            __threadfence();
            atomicAdd(&g_bar, 1u);
            unsigned target = sync_no * RNB;
            while (*((volatile unsigned int*)&g_bar) < target) __nanosleep(64);
            __threadfence();
        }
        __syncthreads();
    }
}

// ---------------- launch ----------------
extern "C" void kernel_launch(void* const* d_in, const int* in_sizes, int n_in,
                              void* d_out, int out_size) {
    const float* emb = (const float*)d_in[0];
    const int*   conn = (const int*)d_in[1];
    // d_in[2] node_mask: unused by the reference
    const float* Wf = (const float*)d_in[3];
    const float* bf = (const float*)d_in[4];
    const float* Wo = (const float*)d_in[5];
    const float* bo = (const float*)d_in[6];
    const float* Wz = (const float*)d_in[7];
    const float* bz = (const float*)d_in[8];
    const float* Tf = (const float*)d_in[9];
    const float* To = (const float*)d_in[10];
    const float* Tz = (const float*)d_in[11];
    float* tree_h = (float*)d_out;

    reset_kernel<<<1, 1>>>();
    setup_kernel<<<1, 512>>>(conn);
    inp0_kernel<<<(BATCH * HDIM) / 256, 256>>>(emb, Wf, bf, Wo, bo, Wz, bz, tree_h);
    v_kernel<<<3 * 256, 256>>>(Tf, To, Tz);
    recur_kernel<<<RNB, RNT>>>(conn, tree_h);
}

// round 5
// speedup vs baseline: 3.2719x; 3.2719x over previous
#include <cuda_runtime.h>
#include <cstdint>
#include <math.h>

#define BATCH 16
#define NNODE 512
#define IDIM  512
#define HDIM  1024

#define RNB 148
#define RNT 256
#define NKC 32          // 32 k-chunks of 32 -> K=1024

// ---------------- device scratch ----------------
__device__ float g_Vcat[3u * HDIM * HDIM];        // [g][r][c], V symmetric
__device__ float g_inp0f[BATCH * HDIM];
__device__ float g_inp0o[BATCH * HDIM];
__device__ float g_inp0z[BATCH * HDIM];
__device__ float g_tree_c[BATCH * NNODE * HDIM];
__device__ int   g_sched[BATCH * NNODE];
__device__ int   g_level_off[NNODE + 1];
__device__ int   g_num_levels;
__device__ unsigned int g_bar;

// ---------------- helpers ----------------
__device__ __forceinline__ void mma_tf32(float* d, const uint32_t* a, const uint32_t* b) {
    asm volatile(
        "mma.sync.aligned.m16n8k8.row.col.f32.tf32.tf32.f32 "
        "{%0,%1,%2,%3}, {%4,%5,%6,%7}, {%8,%9}, {%0,%1,%2,%3};\n"
        : "+f"(d[0]), "+f"(d[1]), "+f"(d[2]), "+f"(d[3])
        : "r"(a[0]), "r"(a[1]), "r"(a[2]), "r"(a[3]), "r"(b[0]), "r"(b[1]));
}
#define CP_ASYNC16(dst_u32, src_ptr) \
    asm volatile("cp.async.cg.shared.global [%0], [%1], 16;" :: "r"(dst_u32), "l"(src_ptr))
#define CP_COMMIT() asm volatile("cp.async.commit_group;" ::: "memory")
#define CP_WAIT(n)  asm volatile("cp.async.wait_group %0;" :: "n"(n) : "memory")

__device__ __forceinline__ float sigf(float x) {
    return __fdividef(1.0f, 1.0f + __expf(-x));
}
__device__ __forceinline__ float tanf_(float x) {
    return 1.0f - __fdividef(2.0f, 1.0f + __expf(2.0f * x));
}

// ---------------- reset (graph replays must start clean) ----------------
__global__ void reset_kernel() { g_bar = 0u; }

// ---------------- setup: levels + counting sort ----------------
__global__ void setup_kernel(const int* __restrict__ conn) {
    __shared__ unsigned short lvl[BATCH][NNODE];
    __shared__ int counts[NNODE];
    __shared__ int offs[NNODE + 1];
    __shared__ int cur[NNODE];
    int tid = threadIdx.x;
    for (int l = tid; l < NNODE; l += blockDim.x) counts[l] = 0;
    __syncthreads();
    if (tid < BATCH) {
        int b = tid;
        lvl[b][0] = 0;
        for (int i = 1; i < NNODE; i++) {
            int p = conn[b * NNODE + i];
            lvl[b][i] = (unsigned short)(lvl[b][p] + 1);
        }
    }
    __syncthreads();
    for (int t = tid; t < BATCH * NNODE; t += blockDim.x) {
        int i = t & (NNODE - 1);
        if (i != 0) atomicAdd(&counts[lvl[t >> 9][i]], 1);
    }
    __syncthreads();
    if (tid == 0) {
        int acc = 0, maxl = 0;
        for (int l = 0; l < NNODE; l++) {
            offs[l] = acc;
            acc += counts[l];
            if (counts[l] > 0) maxl = l;
        }
        offs[NNODE] = acc;
        g_num_levels = maxl + 1;
    }
    __syncthreads();
    for (int l = tid; l <= NNODE; l += blockDim.x) g_level_off[l] = offs[l];
    for (int l = tid; l < NNODE; l += blockDim.x) cur[l] = offs[l];
    __syncthreads();
    for (int t = tid; t < BATCH * NNODE; t += blockDim.x) {
        int b = t >> 9, i = t & (NNODE - 1);
        if (i != 0) {
            int pos = atomicAdd(&cur[lvl[b][i]], 1);
            g_sched[pos] = (b << 16) | i;
        }
    }
}

// ---------------- inp0 (only node 0 matters) + roots ----------------
__global__ void inp0_kernel(const float* __restrict__ emb,
                            const float* __restrict__ Wf, const float* __restrict__ bf,
                            const float* __restrict__ Wo, const float* __restrict__ bo,
                            const float* __restrict__ Wz, const float* __restrict__ bz,
                            float* __restrict__ tree_h) {
    int t = blockIdx.x * blockDim.x + threadIdx.x;
    int b = t >> 10, n = t & (HDIM - 1);
    const float* x = emb + (size_t)b * NNODE * IDIM;
    float af = bf[n], ao = bo[n], az = bz[n];
#pragma unroll 8
    for (int k = 0; k < IDIM; k++) {
        float xv = __ldg(&x[k]);
        af = fmaf(xv, Wf[k * HDIM + n], af);
        ao = fmaf(xv, Wo[k * HDIM + n], ao);
        az = fmaf(xv, Wz[k * HDIM + n], az);
    }
    g_inp0f[t] = af; g_inp0o[t] = ao; g_inp0z[t] = az;
    float f = 1.0f / (1.0f + expf(-af));
    float o = 1.0f / (1.0f + expf(-ao));
    float z = tanhf(az);
    float c = z * (1.0f - f);
    float h = o * tanhf(c);
    tree_h[(b * NNODE) * HDIM + n] = h;
    g_tree_c[(b * NNODE) * HDIM + n] = c;
}

// ---------------- V = T^T T via mma.sync tf32 ----------------
// C[m0+64, n0+64] = sum_k T[k][m] * T[k][n]. A[m][k]=T[k][m], B[n][k]=T[k][n]:
// both read from [k][col] SMEM tiles (pad 68 -> conflict-light).
__global__ void v_kernel(const float* __restrict__ Tf,
                         const float* __restrict__ To,
                         const float* __restrict__ Tz) {
    __shared__ float Ats[32][68];
    __shared__ float Bts[32][68];
    int bid = blockIdx.x;
    int g = bid >> 8, tile = bid & 255;
    int m0 = (tile >> 4) << 6, n0 = (tile & 15) << 6;
    const float* T = (g == 0) ? Tf : (g == 1) ? To : Tz;
    int tid = threadIdx.x, lane = tid & 31, wid = tid >> 5;
    int moff = (wid >> 2) << 5, noff = (wid & 3) << 4;

    float acc[2][2][4];
#pragma unroll
    for (int mf = 0; mf < 2; mf++)
#pragma unroll
        for (int nf = 0; nf < 2; nf++)
#pragma unroll
            for (int j = 0; j < 4; j++) acc[mf][nf][j] = 0.0f;

    for (int k0 = 0; k0 < HDIM; k0 += 32) {
#pragma unroll
        for (int q = 0; q < 2; q++) {
            int fi = tid + (q << 8);
            int kk = fi >> 4, c4 = fi & 15;
            const float* rowp = T + (size_t)(k0 + kk) * HDIM;
            *(float4*)&Ats[kk][c4 << 2] = *(const float4*)(rowp + m0 + (c4 << 2));
            *(float4*)&Bts[kk][c4 << 2] = *(const float4*)(rowp + n0 + (c4 << 2));
        }
        __syncthreads();
#pragma unroll
        for (int ks = 0; ks < 4; ks++) {
            int kb = ks << 3;
            uint32_t a[2][4], b[2][2];
#pragma unroll
            for (int mf = 0; mf < 2; mf++)
#pragma unroll
                for (int i = 0; i < 4; i++) {
                    int m = moff + (mf << 4) + (lane >> 2) + ((i & 1) << 3);
                    int k = kb + (lane & 3) + ((i >> 1) << 2);
                    a[mf][i] = __float_as_uint(Ats[k][m]);
                }
#pragma unroll
            for (int nf = 0; nf < 2; nf++)
#pragma unroll
                for (int i = 0; i < 2; i++) {
                    int n = noff + (nf << 3) + (lane >> 2);
                    int k = kb + (lane & 3) + (i << 2);
                    b[nf][i] = __float_as_uint(Bts[k][n]);
                }
#pragma unroll
            for (int mf = 0; mf < 2; mf++)
#pragma unroll
                for (int nf = 0; nf < 2; nf++)
                    mma_tf32(acc[mf][nf], a[mf], b[nf]);
        }
        __syncthreads();
    }
#pragma unroll
    for (int mf = 0; mf < 2; mf++)
#pragma unroll
        for (int nf = 0; nf < 2; nf++)
#pragma unroll
            for (int rh = 0; rh < 2; rh++) {
                int m = m0 + moff + (mf << 4) + (lane >> 2) + (rh << 3);
                int n = n0 + noff + (nf << 3) + ((lane & 3) << 1);
                float2 v = make_float2(acc[mf][nf][rh << 1], acc[mf][nf][(rh << 1) + 1]);
                *(float2*)&g_Vcat[((size_t)g << 20) + ((size_t)m << 10) + n] = v;
            }
}

// ---------------- persistent mma.sync tf32 recurrence ----------------
// CTA tile: M=64 (gathered parent rows) x N=64 x 3 gates, K=1024 in 32 chunks.
// SMEM: 3 stages x (A 64x32 + 3x B 64x32) floats, XOR-swizzled rows.
#define STG 8192                     // floats per stage

__device__ __forceinline__ uint32_t swz_off(int row, int c4) {
    return (uint32_t)((row << 5) + ((c4 ^ (row & 7)) << 2));   // float index
}

__global__ void __launch_bounds__(RNT, 1)
recur_kernel(const int* __restrict__ conn, float* __restrict__ tree_h) {
    extern __shared__ float sm[];
    int* s_prow = (int*)(sm + 3 * STG);
    int* s_irow = s_prow + 64;
    int* s_bn   = s_prow + 128;
    uint32_t smb = (uint32_t)__cvta_generic_to_shared(sm);

    int tid = threadIdx.x, lane = tid & 31, wid = tid >> 5;
    int moff = (wid >> 2) << 5, noff = (wid & 3) << 4;

    // A-load role: 2 float4 per thread; B-load role: 6 per thread
    int arow = tid >> 3, ac4 = tid & 7;

    int num_lv = g_num_levels;
    unsigned sync_no = 0;

    for (int lv = 1; lv < num_lv; lv++) {
        int off = g_level_off[lv];
        int cnt = g_level_off[lv + 1] - off;
        int mtiles = (cnt + 63) >> 6;
        int total = mtiles << 4;                 // x 16 column slices of 64

        for (int t = blockIdx.x; t < total; t += RNB) {
            int mt = t >> 4, nt = t & 15;
            int n0 = nt << 6;
            int mrel = mt << 6;

            if (tid < 64) {
                int mi = off + mrel + tid;
                int mclamp = off + cnt - 1;
                if (mi > mclamp) mi = mclamp;
                int s = g_sched[mi];
                int b = s >> 16, i = s & 0xFFFF;
                int p = conn[(b << 9) + i];
                s_prow[tid] = ((b << 9) + p) << 10;
                s_irow[tid] = ((b << 9) + i) << 10;
                s_bn[tid]   = b << 10;
            }
            __syncthreads();

            float acc[3][2][2][4];
#pragma unroll
            for (int g = 0; g < 3; g++)
#pragma unroll
                for (int mf = 0; mf < 2; mf++)
#pragma unroll
                    for (int nf = 0; nf < 2; nf++)
#pragma unroll
                        for (int j = 0; j < 4; j++) acc[g][mf][nf][j] = 0.0f;

            // ---- stage loader (cp.async) ----
            // A: 512 f4 (2/thread). B: 1536 f4 (6/thread).
#define LOAD_STAGE(st, kc_) do {                                                       \
    int kb_ = (kc_) << 5;                                                              \
    uint32_t abase = smb + (((uint32_t)(st) * STG) << 2);                              \
    CP_ASYNC16(abase + (swz_off(arow, ac4) << 2),                                      \
               tree_h + s_prow[arow] + kb_ + (ac4 << 2));                              \
    CP_ASYNC16(abase + (swz_off(arow + 32, ac4) << 2),                                 \
               tree_h + s_prow[arow + 32] + kb_ + (ac4 << 2));                         \
    _Pragma("unroll")                                                                  \
    for (int q = 0; q < 6; q++) {                                                      \
        int fi = tid + (q << 8);                                                       \
        int gg = fi >> 9, rem = fi & 511;                                              \
        int row = rem >> 3, c4 = rem & 7;                                              \
        uint32_t bbase = abase + ((2048u + (uint32_t)gg * 2048u) << 2);                \
        CP_ASYNC16(bbase + (swz_off(row, c4) << 2),                                    \
                   g_Vcat + ((size_t)gg << 20) + ((size_t)(n0 + row) << 10)            \
                          + kb_ + (c4 << 2));                                          \
    }                                                                                  \
    CP_COMMIT();                                                                       \
} while (0)

            LOAD_STAGE(0, 0);
            LOAD_STAGE(1, 1);

            for (int kc = 0; kc < NKC; kc++) {
                int st = kc % 3;
                if (kc + 2 < NKC) { LOAD_STAGE((kc + 2) % 3, kc + 2); CP_WAIT(2); }
                else if (kc + 1 < NKC) { CP_WAIT(1); }
                else { CP_WAIT(0); }
                __syncthreads();

                const float* As = sm + st * STG;
#pragma unroll
                for (int ks = 0; ks < 4; ks++) {
                    int kb = ks << 3;
                    uint32_t a[2][4];
#pragma unroll
                    for (int mf = 0; mf < 2; mf++)
#pragma unroll
                        for (int i = 0; i < 4; i++) {
                            int m = moff + (mf << 4) + (lane >> 2) + ((i & 1) << 3);
                            int k = kb + (lane & 3) + ((i >> 1) << 2);
                            a[mf][i] = __float_as_uint(
                                As[(m << 5) + (((k >> 2) ^ (m & 7)) << 2) + (k & 3)]);
                        }
#pragma unroll
                    for (int g = 0; g < 3; g++) {
                        const float* Bs = As + 2048 + g * 2048;
                        uint32_t b[2][2];
#pragma unroll
                        for (int nf = 0; nf < 2; nf++)
#pragma unroll
                            for (int i = 0; i < 2; i++) {
                                int n = noff + (nf << 3) + (lane >> 2);
                                int k = kb + (lane & 3) + (i << 2);
                                b[nf][i] = __float_as_uint(
                                    Bs[(n << 5) + (((k >> 2) ^ (n & 7)) << 2) + (k & 3)]);
                            }
#pragma unroll
                        for (int mf = 0; mf < 2; mf++)
#pragma unroll
                            for (int nf = 0; nf < 2; nf++)
                                mma_tf32(acc[g][mf][nf], a[mf], b[nf]);
                    }
                }
                __syncthreads();
            }

            // ---- fused LSTM-cell epilogue, direct float2 stores ----
#pragma unroll
            for (int mf = 0; mf < 2; mf++)
#pragma unroll
                for (int rh = 0; rh < 2; rh++) {
                    int m = moff + (mf << 4) + (lane >> 2) + (rh << 3);
                    if (mrel + m < cnt) {
                        int prow = s_prow[m], irow = s_irow[m], bn = s_bn[m];
#pragma unroll
                        for (int nf = 0; nf < 2; nf++) {
                            int col = n0 + noff + (nf << 3) + ((lane & 3) << 1);
                            float2 F0 = *(const float2*)(g_inp0f + bn + col);
                            float2 O0 = *(const float2*)(g_inp0o + bn + col);
                            float2 Z0 = *(const float2*)(g_inp0z + bn + col);
                            float2 PC = *(const float2*)(g_tree_c + prow + col);
                            float fa = acc[0][mf][nf][rh << 1], fb = acc[0][mf][nf][(rh << 1) + 1];
                            float oa = acc[1][mf][nf][rh << 1], ob = acc[1][mf][nf][(rh << 1) + 1];
                            float za = acc[2][mf][nf][rh << 1], zb = acc[2][mf][nf][(rh << 1) + 1];
                            float f1 = sigf(fa + F0.x), f2 = sigf(fb + F0.y);
                            float o1 = sigf(oa + O0.x), o2 = sigf(ob + O0.y);
                            float z1 = tanf_(za + Z0.x), z2 = tanf_(zb + Z0.y);
                            float c1 = PC.x * f1 + z1 * (1.0f - f1);
                            float c2 = PC.y * f2 + z2 * (1.0f - f2);
                            float h1 = o1 * tanf_(c1);
                            float h2 = o2 * tanf_(c2);
                            *(float2*)(tree_h + irow + col)   = make_float2(h1, h2);
                            *(float2*)(g_tree_c + irow + col) = make_float2(c1, c2);
                        }
                    }
                }
            __syncthreads();   // protect smem meta before next tile
        }

        // ---- grid barrier (cumulative counter) ----
        sync_no++;
        __syncthreads();
        if (tid == 0) {
            __threadfence();
            atomicAdd(&g_bar, 1u);
            unsigned target = sync_no * RNB;
            while (*((volatile unsigned int*)&g_bar) < target) __nanosleep(64);
            __threadfence();
        }
        __syncthreads();
    }
}

// ---------------- launch ----------------
#define SMEM_RECUR ((3 * STG + 192) * 4)

extern "C" void kernel_launch(void* const* d_in, const int* in_sizes, int n_in,
                              void* d_out, int out_size) {
    const float* emb = (const float*)d_in[0];
    const int*   conn = (const int*)d_in[1];
    const float* Wf = (const float*)d_in[3];
    const float* bf = (const float*)d_in[4];
    const float* Wo = (const float*)d_in[5];
    const float* bo = (const float*)d_in[6];
    const float* Wz = (const float*)d_in[7];
    const float* bz = (const float*)d_in[8];
    const float* Tf = (const float*)d_in[9];
    const float* To = (const float*)d_in[10];
    const float* Tz = (const float*)d_in[11];
    float* tree_h = (float*)d_out;

    cudaFuncSetAttribute(recur_kernel, cudaFuncAttributeMaxDynamicSharedMemorySize, SMEM_RECUR);

    reset_kernel<<<1, 1>>>();
    setup_kernel<<<1, 512>>>(conn);
    inp0_kernel<<<128, 128>>>(emb, Wf, bf, Wo, bo, Wz, bz, tree_h);
    v_kernel<<<3 * 256, 256>>>(Tf, To, Tz);
    recur_kernel<<<RNB, RNT, SMEM_RECUR>>>(conn, tree_h);
}